// round 16
// baseline (speedup 1.0000x reference)
#include <cuda_runtime.h>
#include <cuda_bf16.h>
#include <cstdint>

#define M_ROWS   32768
#define DIM      256
#define KCODES   1024
#define MARGIN   0.45f
#define CHECK_CAP 32768

// Scratch (no cudaMalloc allowed)
__device__ int   g_indices[M_ROWS];
__device__ float g_cnorm[KCODES];
__device__ float g_partials[2048];
__device__ int   g_ncheck;
__device__ int4  g_check[CHECK_CAP];
// Prepacked bf16 codebook in m16n8k16 B-fragment order, tile-major:
// [tile t 0..63][nbp 0..7][ks 0..1][lane 0..31] x uint4  (validated R9-R15)
__device__ uint4  g_bfrag16[32768];   // 512 KB

// ---------------------------------------------------------------------------
// SMEM per CTA: A 32KB | B 3 bufs x 8KB | cnorm 4KB | red 6KB  = 68KB
// 3 CTAs/SM: 3 x 68KB = 204KB < 228KB carveout
// ---------------------------------------------------------------------------
#define SM_AHI   0
#define SM_BF(b) (32768 + (b) * 8192)
#define SM_CN    57344
#define SM_RED   61440
#define SM_TOTAL 69632

__device__ __forceinline__ uint32_t smem_u32(const void* p) {
    uint32_t a;
    asm("{ .reg .u64 t; cvta.to.shared.u64 t, %1; cvt.u32.u64 %0, t; }"
        : "=r"(a) : "l"(p));
    return a;
}
__device__ __forceinline__ void lds128(uint32_t* r, uint32_t addr) {
    asm volatile("ld.shared.v4.u32 {%0,%1,%2,%3}, [%4];"
                 : "=r"(r[0]), "=r"(r[1]), "=r"(r[2]), "=r"(r[3]) : "r"(addr));
}
__device__ __forceinline__ void sts32(uint32_t addr, uint32_t v) {
    asm volatile("st.shared.u32 [%0], %1;" :: "r"(addr), "r"(v) : "memory");
}
__device__ __forceinline__ void cp16(uint32_t dst, const void* src) {
    asm volatile("cp.async.cg.shared.global [%0], [%1], 16;"
                 :: "r"(dst), "l"(src) : "memory");
}
__device__ __forceinline__ void cp_commit() {
    asm volatile("cp.async.commit_group;" ::: "memory");
}
__device__ __forceinline__ void cp_wait1() {
    asm volatile("cp.async.wait_group 1;" ::: "memory");
}
__device__ __forceinline__ void cp_wait0() {
    asm volatile("cp.async.wait_group 0;" ::: "memory");
}

__device__ __forceinline__ void mma_bf16(float* d, const uint32_t* a,
                                         const uint32_t* b) {
    asm volatile(
        "mma.sync.aligned.m16n8k16.row.col.f32.bf16.bf16.f32 "
        "{%0,%1,%2,%3}, {%4,%5,%6,%7}, {%8,%9}, {%0,%1,%2,%3};"
        : "+f"(d[0]), "+f"(d[1]), "+f"(d[2]), "+f"(d[3])
        : "r"(a[0]), "r"(a[1]), "r"(a[2]), "r"(a[3]), "r"(b[0]), "r"(b[1]));
}

__device__ __forceinline__ uint32_t pk_bf16x2(float x, float y) {
    __nv_bfloat162 p;
    p.x = __float2bfloat16(x);
    p.y = __float2bfloat16(y);
    return *reinterpret_cast<uint32_t*>(&p);
}

// insert (d, c) into sorted top-3 with index tie-break
__device__ __forceinline__ void upd3(float& m1, int& i1, float& m2, int& i2,
                                     float& m3, int& i3, float d, int c) {
    if (d < m1 || (d == m1 && c < i1)) {
        m3 = m2; i3 = i2; m2 = m1; i2 = i1; m1 = d; i1 = c;
    } else if (d < m2 || (d == m2 && c < i2)) {
        m3 = m2; i3 = i2; m2 = d; i2 = c;
    } else if (d < m3 || (d == m3 && c < i3)) {
        m3 = d; i3 = c;
    }
}

// ---------------------------------------------------------------------------
// Kernel 0: prepack codebook into bf16 B-fragment order (one shot, 512 KB)
// ---------------------------------------------------------------------------
__global__ void prepack16_kernel(const float* __restrict__ cb) {
    int idx  = blockIdx.x * 256 + threadIdx.x;    // [0, 32768)
    int lane = idx & 31;
    int ks   = (idx >> 5) & 1;
    int nbp  = (idx >> 6) & 7;
    int kt   = (idx >> 9) & 7;
    int chunk = idx >> 12;
    int n0 = chunk * 128 + (2 * nbp) * 8 + (lane >> 2);
    int n1 = n0 + 8;
    int kb = kt * 32 + ks * 16 + 2 * (lane & 3);
    const float* r0 = cb + (size_t)n0 * DIM + kb;
    const float* r1 = cb + (size_t)n1 * DIM + kb;
    uint4 v;
    v.x = pk_bf16x2(r0[0], r0[1]);
    v.y = pk_bf16x2(r0[8], r0[9]);
    v.z = pk_bf16x2(r1[0], r1[1]);
    v.w = pk_bf16x2(r1[8], r1[9]);
    g_bfrag16[idx] = v;
}

// ---------------------------------------------------------------------------
// Kernel 1: codebook norms + zero recheck counter
// ---------------------------------------------------------------------------
__global__ void cnorm_kernel(const float* __restrict__ codebook) {
    if (blockIdx.x == 0 && threadIdx.x == 0) g_ncheck = 0;
    int warp = (blockIdx.x * blockDim.x + threadIdx.x) >> 5;
    int lane = threadIdx.x & 31;
    if (warp >= KCODES) return;
    const float* row = codebook + (size_t)warp * DIM;
    float s = 0.f;
    #pragma unroll
    for (int i = 0; i < DIM / 32; ++i) { float v = row[lane + i * 32]; s += v * v; }
    #pragma unroll
    for (int o = 16; o; o >>= 1) s += __shfl_xor_sync(0xffffffffu, s, o);
    if (lane == 0) g_cnorm[warp] = s;
}

// ---------------------------------------------------------------------------
// Kernel 2: 1-term bf16 distance GEMM + fused TOP-3 argmin + z_e copy.
// Collective 8KB B tiles, 3-stage cp.async ring, CTA barriers, 3 CTAs/SM.
// Rows with coarse gap <= MARGIN get all 3 candidates rechecked exactly.
// ---------------------------------------------------------------------------
__global__ __launch_bounds__(256, 3)
void argmin_bf16(const float* __restrict__ z, const float* __restrict__ cb,
                 float* __restrict__ out) {
    extern __shared__ char sm[];
    const int tid  = threadIdx.x;
    const int lane = tid & 31;
    const int wid  = tid >> 5;
    const int wm   = wid >> 2;      // 0..1 : M group of 32 rows
    const int wn   = wid & 3;       // 0..3 : N group of 32 codes
    const int q    = lane & 3;
    const int rowBase = blockIdx.x * 64;
    const uint32_t sbase = smem_u32(sm);
    const char* bsrc = (const char*)g_bfrag16;

    // cp.async: 8 KB tile = 512 x 16B; thread's 2 chunks, consumer order
    const uint32_t cpo0 = (uint32_t)tid * 16;
    const uint32_t cpo1 = (uint32_t)(256 + tid) * 16;

    // prefetch tiles 0 and 1
    cp16(sbase + SM_BF(0) + cpo0, bsrc + cpo0);
    cp16(sbase + SM_BF(0) + cpo1, bsrc + cpo1);
    cp_commit();
    cp16(sbase + SM_BF(1) + cpo0, bsrc + 8192 + cpo0);
    cp16(sbase + SM_BF(1) + cpo1, bsrc + 8192 + cpo1);
    cp_commit();

    // cnorm -> smem (4KB, one float4 per thread)
    ((float4*)(sm + SM_CN))[tid] = ((const float4*)g_cnorm)[tid];

    // ---- fused z_e copy: this CTA's 64 rows, coalesced float4 ----
    {
        const float4* zsrc = (const float4*)(z + (size_t)rowBase * DIM);
        float4*       zdst = (float4*)(out + (size_t)rowBase * DIM);
        #pragma unroll
        for (int it = 0; it < 16; ++it)
            zdst[it * 256 + tid] = zsrc[it * 256 + tid];
    }

    // ---- A prologue: 64 z rows -> bf16 fragment-order smem (L2-hot now) ----
    #pragma unroll
    for (int it = 0; it < 32; ++it) {
        int idx = it * 256 + tid;              // [0, 8192)
        int reg = idx & 3, l = (idx >> 2) & 31;
        int kstep = (idx >> 7) & 15, mb = idx >> 11;   // mb 0..3
        int row = mb * 16 + (l >> 2) + (reg & 1) * 8;
        int k   = kstep * 16 + 2 * (l & 3) + (reg >> 1) * 8;
        float2 v = *(const float2*)(z + (size_t)(rowBase + row) * DIM + k);
        uint32_t off = (uint32_t)(((mb * 16 + kstep) * 32 + l) * 16 + reg * 4);
        sts32(sbase + SM_AHI + off, pk_bf16x2(v.x, v.y));
    }

    float tm1[4], tm2[4], tm3[4];
    int   ti1[4], ti2[4], ti3[4];
    #pragma unroll
    for (int s = 0; s < 4; ++s) {
        tm1[s] = 3.4e38f; tm2[s] = 3.4e38f; tm3[s] = 3.4e38f;
        ti1[s] = 0x7fffffff; ti2[s] = 0x7fffffff; ti3[s] = 0x7fffffff;
    }

    float acc[2][4][4];
    #pragma unroll
    for (int mt = 0; mt < 2; ++mt)
        #pragma unroll
        for (int nt = 0; nt < 4; ++nt)
            #pragma unroll
            for (int e = 0; e < 4; ++e) acc[mt][nt][e] = 0.f;

    #pragma unroll 1
    for (int t = 0; t < 64; ++t) {             // 8 chunks x 8 k-tiles of 32
        if (t < 63) cp_wait1(); else cp_wait0();   // tile t resident
        __syncthreads();

        // prefetch tile t+2 (two tiles in flight)
        if (t < 62) {
            uint32_t dst = sbase + SM_BF((t + 2) % 3);
            uint32_t src = (uint32_t)(t + 2) * 8192;
            cp16(dst + cpo0, bsrc + src + cpo0);
            cp16(dst + cpo1, bsrc + src + cpo1);
            cp_commit();
        }

        const uint32_t bbuf = sbase + SM_BF(t % 3);
        const int kt = t & 7;
        #pragma unroll
        for (int ks = 0; ks < 2; ++ks) {
            uint32_t a[2][4], bq[2][4];
            #pragma unroll
            for (int mt = 0; mt < 2; ++mt) {
                int mb = wm * 2 + mt;
                lds128(a[mt], sbase + SM_AHI +
                       (uint32_t)(((mb * 16 + kt * 2 + ks) * 32 + lane) * 16));
            }
            #pragma unroll
            for (int pp = 0; pp < 2; ++pp) {
                int nbp = wn * 2 + pp;
                lds128(bq[pp], bbuf +
                       (uint32_t)(((nbp * 2 + ks) * 32 + lane) * 16));
            }
            #pragma unroll
            for (int mt = 0; mt < 2; ++mt)
                #pragma unroll
                for (int pp = 0; pp < 2; ++pp) {
                    mma_bf16(acc[mt][pp * 2 + 0], a[mt], &bq[pp][0]);
                    mma_bf16(acc[mt][pp * 2 + 1], a[mt], &bq[pp][2]);
                }
        }

        // chunk epilogue every 8 tiles (cnorm from smem, top-3 update)
        if ((t & 7) == 7) {
            const int codeBase = (t >> 3) * 128;
            #pragma unroll
            for (int mt = 0; mt < 2; ++mt)
                #pragma unroll
                for (int nt = 0; nt < 4; ++nt) {
                    int col = codeBase + wn * 32 + nt * 8 + 2 * q;
                    float c0 = *(const float*)(sm + SM_CN + col * 4);
                    float c1 = *(const float*)(sm + SM_CN + col * 4 + 4);
                    #pragma unroll
                    for (int hh = 0; hh < 2; ++hh) {
                        int s = mt * 2 + hh;
                        float d0 = fmaf(-2.f, acc[mt][nt][hh * 2 + 0], c0);
                        float d1 = fmaf(-2.f, acc[mt][nt][hh * 2 + 1], c1);
                        upd3(tm1[s], ti1[s], tm2[s], ti2[s], tm3[s], ti3[s],
                             d0, col);
                        upd3(tm1[s], ti1[s], tm2[s], ti2[s], tm3[s], ti3[s],
                             d1, col + 1);
                    }
                }
            #pragma unroll
            for (int mt = 0; mt < 2; ++mt)
                #pragma unroll
                for (int nt = 0; nt < 4; ++nt)
                    #pragma unroll
                    for (int e = 0; e < 4; ++e) acc[mt][nt][e] = 0.f;
        }
    }

    // ---- final reduce: quad shuffle insertion-merge, then cross-warp smem ----
    float4* red4 = (float4*)(sm + SM_RED);          // [64 rows][4 wn]
    float2* red2 = (float2*)(sm + SM_RED + 4096);   // [64 rows][4 wn]
    __syncthreads();
    #pragma unroll
    for (int s = 0; s < 4; ++s) {
        float m1 = tm1[s], m2 = tm2[s], m3 = tm3[s];
        int   i1 = ti1[s], i2 = ti2[s], i3 = ti3[s];
        #pragma unroll
        for (int off = 1; off <= 2; off <<= 1) {
            float om1 = __shfl_xor_sync(0xffffffffu, m1, off);
            int   oi1 = __shfl_xor_sync(0xffffffffu, i1, off);
            float om2 = __shfl_xor_sync(0xffffffffu, m2, off);
            int   oi2 = __shfl_xor_sync(0xffffffffu, i2, off);
            float om3 = __shfl_xor_sync(0xffffffffu, m3, off);
            int   oi3 = __shfl_xor_sync(0xffffffffu, i3, off);
            upd3(m1, i1, m2, i2, m3, i3, om1, oi1);
            upd3(m1, i1, m2, i2, m3, i3, om2, oi2);
            upd3(m1, i1, m2, i2, m3, i3, om3, oi3);
        }
        if (q == 0) {
            int mt = s >> 1, hh = s & 1;
            int row = wm * 32 + mt * 16 + hh * 8 + (lane >> 2);
            red4[row * 4 + wn] = make_float4(m1, __int_as_float(i1),
                                             m2, __int_as_float(i2));
            red2[row * 4 + wn] = make_float2(m3, __int_as_float(i3));
        }
    }
    __syncthreads();

    if (tid < 64) {
        float4 p = red4[tid * 4 + 0];
        float2 p2 = red2[tid * 4 + 0];
        float m1 = p.x, m2 = p.z, m3 = p2.x;
        int   i1 = __float_as_int(p.y), i2 = __float_as_int(p.w);
        int   i3 = __float_as_int(p2.y);
        #pragma unroll
        for (int w = 1; w < 4; ++w) {
            float4 o = red4[tid * 4 + w];
            float2 o2 = red2[tid * 4 + w];
            upd3(m1, i1, m2, i2, m3, i3, o.x, __float_as_int(o.y));
            upd3(m1, i1, m2, i2, m3, i3, o.z, __float_as_int(o.w));
            upd3(m1, i1, m2, i2, m3, i3, o2.x, __float_as_int(o2.y));
        }
        int row = rowBase + tid;
        g_indices[row] = i1;
        if (m2 - m1 <= MARGIN) {
            int slot = atomicAdd(&g_ncheck, 1);
            if (slot < CHECK_CAP) g_check[slot] = make_int4(row, i1, i2, i3);
        }
    }
}

// ---------------------------------------------------------------------------
// Kernel 3: exact fp32 3-candidate recheck of flagged rows (warp per entry)
// ---------------------------------------------------------------------------
__global__ void recheck_kernel(const float* __restrict__ z,
                               const float* __restrict__ cb) {
    int nw = (gridDim.x * blockDim.x) >> 5;
    int w = (blockIdx.x * blockDim.x + threadIdx.x) >> 5;
    int lane = threadIdx.x & 31;
    int n = g_ncheck; if (n > CHECK_CAP) n = CHECK_CAP;
    for (int e = w; e < n; e += nw) {
        int4 ent = g_check[e];
        const float* zr = z  + (size_t)ent.x * DIM;
        const float* e1 = cb + (size_t)ent.y * DIM;
        const float* e2 = cb + (size_t)ent.z * DIM;
        const float* e3 = cb + (size_t)ent.w * DIM;
        float d1 = 0.f, d2 = 0.f, d3 = 0.f;
        for (int i = lane; i < DIM; i += 32) {
            float zv = zr[i];
            float a = zv - e1[i]; d1 = fmaf(a, a, d1);
            float b = zv - e2[i]; d2 = fmaf(b, b, d2);
            float c = zv - e3[i]; d3 = fmaf(c, c, d3);
        }
        #pragma unroll
        for (int o = 16; o; o >>= 1) {
            d1 += __shfl_xor_sync(0xffffffffu, d1, o);
            d2 += __shfl_xor_sync(0xffffffffu, d2, o);
            d3 += __shfl_xor_sync(0xffffffffu, d3, o);
        }
        if (lane == 0) {
            float bm = d1; int bi = ent.y;
            if (d2 < bm || (d2 == bm && ent.z < bi)) { bm = d2; bi = ent.z; }
            if (d3 < bm || (d3 == bm && ent.w < bi)) { bm = d3; bi = ent.w; }
            g_indices[ent.x] = bi;
        }
    }
}

// ---------------------------------------------------------------------------
// Kernel 4: gather z_q (z_q_st == z_q) + partial loss sums.
// z_e was already copied to out by argmin_bf16.
// ---------------------------------------------------------------------------
__global__ void gather_kernel(const float* __restrict__ z,
                              const float* __restrict__ cb,
                              float* __restrict__ out) {
    const int TOTAL4 = (M_ROWS * DIM) / 4;
    float* __restrict__ out_zq = out + (size_t)M_ROWS * DIM + 1;

    float lsum = 0.f;
    int stride = gridDim.x * blockDim.x;
    for (int t = blockIdx.x * blockDim.x + threadIdx.x; t < TOTAL4; t += stride) {
        float4 ze = ((const float4*)z)[t];
        int row = t >> 6;
        int idx = g_indices[row];
        float4 qv = ((const float4*)cb)[(size_t)idx * 64 + (t & 63)];
        float dx = qv.x - ze.x, dy = qv.y - ze.y;
        float dz = qv.z - ze.z, dw = qv.w - ze.w;
        lsum += dx * dx + dy * dy + dz * dz + dw * dw;
        size_t b = (size_t)t * 4;
        out_zq[b + 0] = qv.x; out_zq[b + 1] = qv.y;
        out_zq[b + 2] = qv.z; out_zq[b + 3] = qv.w;
    }

    __shared__ float red[256];
    red[threadIdx.x] = lsum;
    __syncthreads();
    #pragma unroll
    for (int s = 128; s; s >>= 1) {
        if (threadIdx.x < s) red[threadIdx.x] += red[threadIdx.x + s];
        __syncthreads();
    }
    if (threadIdx.x == 0) g_partials[blockIdx.x] = red[0];
}

// ---------------------------------------------------------------------------
// Kernel 5: deterministic final loss
// ---------------------------------------------------------------------------
__global__ void finalize_kernel(float* __restrict__ out) {
    __shared__ float red[1024];
    int t = threadIdx.x;
    red[t] = g_partials[t] + g_partials[t + 1024];
    __syncthreads();
    #pragma unroll
    for (int s = 512; s; s >>= 1) {
        if (t < s) red[t] += red[t + s];
        __syncthreads();
    }
    if (t == 0)
        out[(size_t)M_ROWS * DIM] = 2.0f * red[0] / (float)(M_ROWS * DIM);
}

// ---------------------------------------------------------------------------
extern "C" void kernel_launch(void* const* d_in, const int* in_sizes, int n_in,
                              void* d_out, int out_size) {
    const float* z  = (const float*)d_in[0];
    const float* cb = (const float*)d_in[1];
    float* out = (float*)d_out;

    cudaFuncSetAttribute(argmin_bf16,
                         cudaFuncAttributeMaxDynamicSharedMemorySize, SM_TOTAL);

    prepack16_kernel<<<128, 256>>>(cb);
    cnorm_kernel    <<<KCODES / 8, 256>>>(cb);
    argmin_bf16     <<<M_ROWS / 64, 256, SM_TOTAL>>>(z, cb, out);
    recheck_kernel  <<<256, 256>>>(z, cb);
    gather_kernel   <<<2048, 256>>>(z, cb, out);
    finalize_kernel <<<1, 1024>>>(out);
}

// round 17
// speedup vs baseline: 1.0362x; 1.0362x over previous
#include <cuda_runtime.h>
#include <cuda_bf16.h>
#include <cstdint>

#define M_ROWS   32768
#define DIM      256
#define KCODES   1024
#define MARGIN   0.3f
#define CHECK_CAP 32768

// Scratch (no cudaMalloc allowed)
__device__ int   g_indices[M_ROWS];
__device__ float g_cnorm[KCODES];
__device__ float g_partials[2048];
__device__ int   g_ncheck;
__device__ int   g_done;
__device__ int4  g_check[CHECK_CAP];
// Prepacked bf16 codebook in m16n8k16 B-fragment order, tile-major:
// [tile t 0..63][nbp 0..7][ks 0..1][lane 0..31] x uint4  (validated R9-R16)
// warp wn's per-tile slice = contiguous 1KB at (t*8 + wn)*1024
__device__ uint4  g_bfrag16[32768];   // 512 KB

// ---------------------------------------------------------------------------
// SMEM per CTA: A_hi 32KB | A_lo 32KB | B 8 warps x 3 bufs x 1KB | red 8KB
// (byte-identical layout to R12, the best-total config)
// ---------------------------------------------------------------------------
#define SM_AHI   0
#define SM_ALO   32768
#define SM_B     65536
#define SM_RED   90112
#define SM_TOTAL 98304

__device__ __forceinline__ uint32_t smem_u32(const void* p) {
    uint32_t a;
    asm("{ .reg .u64 t; cvta.to.shared.u64 t, %1; cvt.u32.u64 %0, t; }"
        : "=r"(a) : "l"(p));
    return a;
}
__device__ __forceinline__ void lds128(uint32_t* r, uint32_t addr) {
    asm volatile("ld.shared.v4.u32 {%0,%1,%2,%3}, [%4];"
                 : "=r"(r[0]), "=r"(r[1]), "=r"(r[2]), "=r"(r[3]) : "r"(addr));
}
__device__ __forceinline__ void sts32(uint32_t addr, uint32_t v) {
    asm volatile("st.shared.u32 [%0], %1;" :: "r"(addr), "r"(v) : "memory");
}
__device__ __forceinline__ void cp16(uint32_t dst, const void* src) {
    asm volatile("cp.async.cg.shared.global [%0], [%1], 16;"
                 :: "r"(dst), "l"(src) : "memory");
}
__device__ __forceinline__ void cp_commit() {
    asm volatile("cp.async.commit_group;" ::: "memory");
}
__device__ __forceinline__ void cp_wait1() {
    asm volatile("cp.async.wait_group 1;" ::: "memory");
}
__device__ __forceinline__ void cp_wait0() {
    asm volatile("cp.async.wait_group 0;" ::: "memory");
}

__device__ __forceinline__ void mma_bf16(float* d, const uint32_t* a,
                                         const uint32_t* b) {
    asm volatile(
        "mma.sync.aligned.m16n8k16.row.col.f32.bf16.bf16.f32 "
        "{%0,%1,%2,%3}, {%4,%5,%6,%7}, {%8,%9}, {%0,%1,%2,%3};"
        : "+f"(d[0]), "+f"(d[1]), "+f"(d[2]), "+f"(d[3])
        : "r"(a[0]), "r"(a[1]), "r"(a[2]), "r"(a[3]), "r"(b[0]), "r"(b[1]));
}

__device__ __forceinline__ uint32_t pk_bf16x2(float x, float y) {
    __nv_bfloat162 p;
    p.x = __float2bfloat16(x);
    p.y = __float2bfloat16(y);
    return *reinterpret_cast<uint32_t*>(&p);
}

__device__ __forceinline__ void upd2(float& m1, int& i1, float& m2, int& i2,
                                     float d, int c) {
    if (d < m1 || (d == m1 && c < i1)) { m2 = m1; i2 = i1; m1 = d; i1 = c; }
    else if (d < m2 || (d == m2 && c < i2)) { m2 = d; i2 = c; }
}
__device__ __forceinline__ void merge2(float& m1, int& i1, float& m2, int& i2,
                                       float om1, int oi1, float om2, int oi2) {
    if (om1 < m1 || (om1 == m1 && oi1 < i1)) {
        float c = m1; int ci = i1;
        m1 = om1; i1 = oi1;
        if (om2 < c || (om2 == c && oi2 < ci)) { m2 = om2; i2 = oi2; }
        else                                   { m2 = c;   i2 = ci;  }
    } else if (om1 < m2 || (om1 == m2 && oi1 < i2)) {
        m2 = om1; i2 = oi1;
    }
}

// ---------------------------------------------------------------------------
// Kernel 0 (merged): blocks 0-127 prepack the codebook into bf16 B-fragment
// order; blocks 128-255 compute codebook norms. Counters zeroed by block 0.
// ---------------------------------------------------------------------------
__global__ void init_kernel(const float* __restrict__ cb) {
    if (blockIdx.x == 0 && threadIdx.x == 0) { g_ncheck = 0; g_done = 0; }

    if (blockIdx.x < 128) {
        int idx  = blockIdx.x * 256 + threadIdx.x;    // [0, 32768)
        int lane = idx & 31;
        int ks   = (idx >> 5) & 1;
        int nbp  = (idx >> 6) & 7;
        int kt   = (idx >> 9) & 7;
        int chunk = idx >> 12;
        int n0 = chunk * 128 + (2 * nbp) * 8 + (lane >> 2);
        int n1 = n0 + 8;
        int kb = kt * 32 + ks * 16 + 2 * (lane & 3);
        const float* r0 = cb + (size_t)n0 * DIM + kb;
        const float* r1 = cb + (size_t)n1 * DIM + kb;
        uint4 v;
        v.x = pk_bf16x2(r0[0], r0[1]);
        v.y = pk_bf16x2(r0[8], r0[9]);
        v.z = pk_bf16x2(r1[0], r1[1]);
        v.w = pk_bf16x2(r1[8], r1[9]);
        g_bfrag16[idx] = v;
    } else {
        int warp = ((blockIdx.x - 128) * 256 + threadIdx.x) >> 5;  // [0,1024)
        int lane = threadIdx.x & 31;
        const float* row = cb + (size_t)warp * DIM;
        float s = 0.f;
        #pragma unroll
        for (int i = 0; i < DIM / 32; ++i) {
            float v = row[lane + i * 32];
            s += v * v;
        }
        #pragma unroll
        for (int o = 16; o; o >>= 1) s += __shfl_xor_sync(0xffffffffu, s, o);
        if (lane == 0) g_cnorm[warp] = s;
    }
}

// ---------------------------------------------------------------------------
// Kernel 1: 2-term split-bf16 distance GEMM (A = hi+lo exact, B bf16) with
// fused top-2 argmin. R12-verbatim (best measured total config).
// ---------------------------------------------------------------------------
__global__ __launch_bounds__(256, 2)
void argmin_mma2(const float* __restrict__ z, const float* __restrict__ cb) {
    extern __shared__ char sm[];
    const int tid  = threadIdx.x;
    const int lane = tid & 31;
    const int wn   = tid >> 5;           // 0..7 : code-slice owner
    const int q    = lane & 3;
    const int rowBase = blockIdx.x * 64;
    const uint32_t sbase = smem_u32(sm);
    const char* bsrc = (const char*)g_bfrag16;

    const uint32_t myB = sbase + SM_B + (uint32_t)wn * 3072;
    const uint32_t co0 = (uint32_t)lane * 16;
    const uint32_t co1 = co0 + 512;

    // prefetch tiles 0,1 into bufs 0,1 (warp-private groups)
    {
        const char* s0 = bsrc + (0 * 8 + wn) * 1024;
        cp16(myB + 0 * 1024 + co0, s0 + co0);
        cp16(myB + 0 * 1024 + co1, s0 + co1);
        cp_commit();
        const char* s1 = bsrc + (1 * 8 + wn) * 1024;
        cp16(myB + 1 * 1024 + co0, s1 + co0);
        cp16(myB + 1 * 1024 + co1, s1 + co1);
        cp_commit();
    }

    // ---- A prologue: 64 z rows -> hi/lo bf16 fragment-order smem ----
    #pragma unroll
    for (int it = 0; it < 32; ++it) {
        int idx = it * 256 + tid;              // [0, 8192)
        int reg = idx & 3, l = (idx >> 2) & 31;
        int kstep = (idx >> 7) & 15, mb = idx >> 11;   // mb 0..3
        int row = mb * 16 + (l >> 2) + (reg & 1) * 8;
        int k   = kstep * 16 + 2 * (l & 3) + (reg >> 1) * 8;
        float2 v = *(const float2*)(z + (size_t)(rowBase + row) * DIM + k);
        __nv_bfloat16 hx = __float2bfloat16(v.x);
        __nv_bfloat16 hy = __float2bfloat16(v.y);
        float lx = v.x - __bfloat162float(hx);
        float ly = v.y - __bfloat162float(hy);
        uint32_t off = (uint32_t)(((mb * 16 + kstep) * 32 + l) * 16 + reg * 4);
        __nv_bfloat162 hp; hp.x = hx; hp.y = hy;
        sts32(sbase + SM_AHI + off, *reinterpret_cast<uint32_t*>(&hp));
        sts32(sbase + SM_ALO + off, pk_bf16x2(lx, ly));
    }
    __syncthreads();                           // only CTA barrier pre-mainloop

    float tm1[8], tm2[8];
    int   ti1[8], ti2[8];
    #pragma unroll
    for (int s = 0; s < 8; ++s) {
        tm1[s] = 3.4e38f; tm2[s] = 3.4e38f;
        ti1[s] = 0x7fffffff; ti2[s] = 0x7fffffff;
    }

    float acc[4][2][4];
    #pragma unroll
    for (int mt = 0; mt < 4; ++mt)
        #pragma unroll
        for (int nt = 0; nt < 2; ++nt)
            #pragma unroll
            for (int e = 0; e < 4; ++e) acc[mt][nt][e] = 0.f;

    #pragma unroll 1
    for (int t = 0; t < 64; ++t) {             // 8 chunks x 8 k-tiles of 32
        if (t < 63) cp_wait1(); else cp_wait0();
        __syncwarp();

        if (t + 2 < 64) {                      // prefetch t+2 (warp-private)
            const char* s2 = bsrc + ((t + 2) * 8 + wn) * 1024;
            uint32_t d2 = myB + (uint32_t)((t + 2) % 3) * 1024;
            cp16(d2 + co0, s2 + co0);
            cp16(d2 + co1, s2 + co1);
            cp_commit();
        }

        const uint32_t bbuf = myB + (uint32_t)(t % 3) * 1024;
        const int kt = t & 7;
        #pragma unroll
        for (int ks = 0; ks < 2; ++ks) {
            uint32_t bq[4];
            lds128(bq, bbuf + (uint32_t)ks * 512 + co0);
            #pragma unroll
            for (int mt = 0; mt < 4; ++mt) {
                uint32_t aoff = (uint32_t)(((mt * 16 + kt * 2 + ks) * 32 + lane) * 16);
                uint32_t ah[4], al[4];
                lds128(ah, sbase + SM_AHI + aoff);
                mma_bf16(acc[mt][0], ah, &bq[0]);
                mma_bf16(acc[mt][1], ah, &bq[2]);
                lds128(al, sbase + SM_ALO + aoff);
                mma_bf16(acc[mt][0], al, &bq[0]);
                mma_bf16(acc[mt][1], al, &bq[2]);
            }
        }

        // chunk epilogue every 8 tiles
        if ((t & 7) == 7) {
            const int codeBase = (t >> 3) * 128;
            #pragma unroll
            for (int mt = 0; mt < 4; ++mt)
                #pragma unroll
                for (int nt = 0; nt < 2; ++nt) {
                    int col = codeBase + wn * 16 + nt * 8 + 2 * q;
                    float c0 = g_cnorm[col], c1 = g_cnorm[col + 1];
                    #pragma unroll
                    for (int hh = 0; hh < 2; ++hh) {
                        int s = mt * 2 + hh;
                        float d0 = fmaf(-2.f, acc[mt][nt][hh * 2 + 0], c0);
                        float d1 = fmaf(-2.f, acc[mt][nt][hh * 2 + 1], c1);
                        upd2(tm1[s], ti1[s], tm2[s], ti2[s], d0, col);
                        upd2(tm1[s], ti1[s], tm2[s], ti2[s], d1, col + 1);
                    }
                }
            #pragma unroll
            for (int mt = 0; mt < 4; ++mt)
                #pragma unroll
                for (int nt = 0; nt < 2; ++nt)
                    #pragma unroll
                    for (int e = 0; e < 4; ++e) acc[mt][nt][e] = 0.f;
        }
    }

    // ---- final reduce: quad shuffle, then across the 8 wn warps via SMEM ----
    float4* red = (float4*)(sm + SM_RED);      // [64 rows][8 wn] = 8KB
    #pragma unroll
    for (int s = 0; s < 8; ++s) {
        float m1 = tm1[s], m2 = tm2[s];
        int   i1 = ti1[s], i2 = ti2[s];
        #pragma unroll
        for (int off = 1; off <= 2; off <<= 1) {
            float om1 = __shfl_xor_sync(0xffffffffu, m1, off);
            int   oi1 = __shfl_xor_sync(0xffffffffu, i1, off);
            float om2 = __shfl_xor_sync(0xffffffffu, m2, off);
            int   oi2 = __shfl_xor_sync(0xffffffffu, i2, off);
            merge2(m1, i1, m2, i2, om1, oi1, om2, oi2);
        }
        if (q == 0) {
            int mt = s >> 1, hh = s & 1;
            int row = mt * 16 + hh * 8 + (lane >> 2);
            red[row * 8 + wn] = make_float4(m1, __int_as_float(i1),
                                            m2, __int_as_float(i2));
        }
    }
    __syncthreads();

    if (tid < 64) {
        float4 p = red[tid * 8 + 0];
        float m1 = p.x, m2 = p.z;
        int   i1 = __float_as_int(p.y), i2 = __float_as_int(p.w);
        #pragma unroll
        for (int w = 1; w < 8; ++w) {
            float4 o = red[tid * 8 + w];
            merge2(m1, i1, m2, i2, o.x, __float_as_int(o.y),
                   o.z, __float_as_int(o.w));
        }
        int row = rowBase + tid;
        g_indices[row] = i1;
        if (m2 - m1 <= MARGIN) {
            int slot = atomicAdd(&g_ncheck, 1);
            if (slot < CHECK_CAP) g_check[slot] = make_int4(row, i1, i2, 0);
        }
    }
}

// ---------------------------------------------------------------------------
// Kernel 2: exact fp32 pair recheck of flagged rows (one warp per entry)
// ---------------------------------------------------------------------------
__global__ void recheck_kernel(const float* __restrict__ z,
                               const float* __restrict__ cb) {
    int nw = (gridDim.x * blockDim.x) >> 5;
    int w = (blockIdx.x * blockDim.x + threadIdx.x) >> 5;
    int lane = threadIdx.x & 31;
    int n = g_ncheck; if (n > CHECK_CAP) n = CHECK_CAP;
    for (int e = w; e < n; e += nw) {
        int4 ent = g_check[e];
        const float* zr = z  + (size_t)ent.x * DIM;
        const float* e1 = cb + (size_t)ent.y * DIM;
        const float* e2 = cb + (size_t)ent.z * DIM;
        float d1 = 0.f, d2 = 0.f;
        for (int i = lane; i < DIM; i += 32) {
            float zv = zr[i];
            float a = zv - e1[i]; d1 += a * a;
            float b = zv - e2[i]; d2 += b * b;
        }
        #pragma unroll
        for (int o = 16; o; o >>= 1) {
            d1 += __shfl_xor_sync(0xffffffffu, d1, o);
            d2 += __shfl_xor_sync(0xffffffffu, d2, o);
        }
        if (lane == 0) {
            int best = (d1 < d2) ? ent.y : ((d2 < d1) ? ent.z
                        : (ent.y < ent.z ? ent.y : ent.z));
            g_indices[ent.x] = best;
        }
    }
}

// ---------------------------------------------------------------------------
// Kernel 3: copy z_e, gather z_q (z_q_st == z_q), partial loss sums,
// and FUSED deterministic final loss (last CTA reduces all partials).
// ---------------------------------------------------------------------------
__global__ void gather_kernel(const float* __restrict__ z,
                              const float* __restrict__ cb,
                              float* __restrict__ out) {
    const int TOTAL4 = (M_ROWS * DIM) / 4;
    float* __restrict__ out_ze = out;
    float* __restrict__ out_zq = out + (size_t)M_ROWS * DIM + 1;

    float lsum = 0.f;
    int stride = gridDim.x * blockDim.x;
    for (int t = blockIdx.x * blockDim.x + threadIdx.x; t < TOTAL4; t += stride) {
        float4 ze = ((const float4*)z)[t];
        ((float4*)out_ze)[t] = ze;
        int row = t >> 6;
        int idx = g_indices[row];
        float4 qv = ((const float4*)cb)[(size_t)idx * 64 + (t & 63)];
        float dx = qv.x - ze.x, dy = qv.y - ze.y;
        float dz = qv.z - ze.z, dw = qv.w - ze.w;
        lsum += dx * dx + dy * dy + dz * dz + dw * dw;
        size_t b = (size_t)t * 4;
        out_zq[b + 0] = qv.x; out_zq[b + 1] = qv.y;
        out_zq[b + 2] = qv.z; out_zq[b + 3] = qv.w;
    }

    __shared__ float red[256];
    __shared__ int   s_last;
    red[threadIdx.x] = lsum;
    __syncthreads();
    #pragma unroll
    for (int s = 128; s; s >>= 1) {
        if (threadIdx.x < s) red[threadIdx.x] += red[threadIdx.x + s];
        __syncthreads();
    }
    if (threadIdx.x == 0) {
        g_partials[blockIdx.x] = red[0];
        __threadfence();
        s_last = (atomicAdd(&g_done, 1) == (int)gridDim.x - 1);
    }
    __syncthreads();

    if (s_last) {
        // last CTA: deterministic reduction of all 2048 partials
        float s = 0.f;
        #pragma unroll
        for (int i = 0; i < 8; ++i)
            s += g_partials[threadIdx.x + i * 256];
        red[threadIdx.x] = s;
        __syncthreads();
        #pragma unroll
        for (int st = 128; st; st >>= 1) {
            if (threadIdx.x < st) red[threadIdx.x] += red[threadIdx.x + st];
            __syncthreads();
        }
        if (threadIdx.x == 0)
            out[(size_t)M_ROWS * DIM] = 2.0f * red[0] / (float)(M_ROWS * DIM);
    }
}

// ---------------------------------------------------------------------------
extern "C" void kernel_launch(void* const* d_in, const int* in_sizes, int n_in,
                              void* d_out, int out_size) {
    const float* z  = (const float*)d_in[0];
    const float* cb = (const float*)d_in[1];
    float* out = (float*)d_out;

    cudaFuncSetAttribute(argmin_mma2,
                         cudaFuncAttributeMaxDynamicSharedMemorySize, SM_TOTAL);

    init_kernel    <<<256, 256>>>(cb);
    argmin_mma2    <<<M_ROWS / 64, 256, SM_TOTAL>>>(z, cb);
    recheck_kernel <<<64, 256>>>(z, cb);
    gather_kernel  <<<2048, 256>>>(z, cb, out);
}